// round 16
// baseline (speedup 1.0000x reference)
#include <cuda_runtime.h>
#include <cstdint>

// x: [32, 512, 56, 56] fp32, chunks of 8 batches (51.4 MB, L2-resident).
// 5 launches. SA(c) = 8 FC1 blocks (compute chunk c's hidden units from raw
// sums completed last launch; set epoch-tagged flags) + 3136 streaming blocks
// (R11-proven: coalesced scale chunk c from L2 + DRAM write, fused reduce-
// accumulate chunk c+1 from DRAM; FC2-only prologue gated on the flag, only
// the STORES wait). No fences after streaming stores anywhere.
// DRAM total: 410 MB vs 616 MB unchunked.

#define C            512
#define CR           32
#define SPATIAL4     784                        // f4 per slice
#define CHUNK_B      8
#define NCHUNK       4
#define CHUNK_SLICES 4096
#define CHUNK_F4     (CHUNK_SLICES * SPATIAL4)  // 3,211,264
#define NSTREAM      3136                       // CHUNK_F4 / 1024
#define BLKS_PER_BATCH 392                      // 401408 f4 / 1024

__device__ float d_sq[32 * C];                  // raw per-slice sums
__device__ float d_hid[32 * CR];                // per-batch hidden units
__device__ unsigned int d_flag[32];             // epoch-tagged hid-ready flags
__device__ unsigned int d_epoch;                // bumped once per replay (R0)

// ---------------------------------------------------------------------------
// R0: one block per slice of chunk 0 (proven 6.28 TB/s shape). Block 0 bumps
// the replay epoch.
// ---------------------------------------------------------------------------
__global__ __launch_bounds__(128) void se_reduce0(const float* __restrict__ x)
{
    if (blockIdx.x == 0 && threadIdx.x == 0)
        atomicAdd(&d_epoch, 1u);

    const int s = blockIdx.x;                   // slice in chunk 0
    const float4* __restrict__ p =
        reinterpret_cast<const float4*>(x) + (size_t)s * SPATIAL4;

    float acc = 0.0f;
    #pragma unroll
    for (int i = threadIdx.x; i < SPATIAL4; i += 128) {
        float4 v = p[i];
        acc += (v.x + v.y) + (v.z + v.w);
    }
    #pragma unroll
    for (int off = 16; off > 0; off >>= 1)
        acc += __shfl_down_sync(0xFFFFFFFFu, acc, off);

    __shared__ float ws[4];
    const int lane = threadIdx.x & 31;
    if (lane == 0) ws[threadIdx.x >> 5] = acc;
    __syncthreads();
    if (threadIdx.x == 0)
        d_sq[s] = ws[0] + ws[1] + ws[2] + ws[3];
}

// ---------------------------------------------------------------------------
// SA: blocks 0..7 = FC1 producers; blocks 8.. = streaming (R11 shape).
// ---------------------------------------------------------------------------
__global__ __launch_bounds__(256) void se_sa(
    const float* __restrict__ x,
    float* __restrict__ out,
    const float* __restrict__ w1, const float* __restrict__ b1,
    const float* __restrict__ w2, const float* __restrict__ b2,
    int sc, int rc)
{
    const int tid  = threadIdx.x;
    const int lane = tid & 31;
    const int wid  = tid >> 5;

    const unsigned int tag = __ldcg(&d_epoch) * 8u + (unsigned int)sc;

    // ======================= FC1 producer blocks ===========================
    if (blockIdx.x < CHUNK_B) {
        const int gb = sc * CHUNK_B + blockIdx.x;       // global batch
        const float* __restrict__ sqp = d_sq + (size_t)gb * C;

        #pragma unroll
        for (int r = 0; r < 4; ++r) {                   // warp w -> units 4w..
            const int u = wid * 4 + r;
            const float* __restrict__ wrow = w1 + (size_t)u * C;
            float a = 0.0f;
            #pragma unroll
            for (int k = 0; k < 16; ++k) {
                const int idx = lane + 32 * k;
                a = fmaf(__ldcg(&sqp[idx]), __ldg(&wrow[idx]), a);
            }
            #pragma unroll
            for (int off = 16; off > 0; off >>= 1)
                a += __shfl_down_sync(0xFFFFFFFFu, a, off);
            if (lane == 0) {
                d_hid[gb * CR + u] =
                    fmaxf(a * (1.0f / 3136.0f) + __ldg(&b1[u]), 0.0f);
                __threadfence();                        // publish my writes
            }
        }
        __syncthreads();
        if (tid == 0) {
            __threadfence();
            atomicExch(&d_flag[gb], tag);               // epoch-tagged ready
        }
        // zero this batch's raw sums for the next replay's accumulation
        for (int i = tid; i < C; i += 256)
            d_sq[gb * C + i] = 0.0f;
        return;
    }

    // ======================= streaming blocks ==============================
    const int rid = blockIdx.x - CHUNK_B;               // 0..3135
    const unsigned int i0b = rid * 1024u;
    const unsigned int i0  = i0b + tid;
    const int batch    = rid / BLKS_PER_BATCH;          // 0..7 (no straddle)
    const int slice_lo = (int)(i0b / 784u);
    const unsigned int bd1 = (unsigned int)(slice_lo + 1) * 784u;
    const unsigned int bd2 = (unsigned int)(slice_lo + 2) * 784u;

    const float4* __restrict__ x4 = reinterpret_cast<const float4*>(x);
    float4*       __restrict__ o4 = reinterpret_cast<float4*>(out);

    const unsigned int base_s = (unsigned int)sc * CHUNK_F4 + i0;

    // batched loads first: 4 scale f4 (L2 hits) + 4 reduce f4 (DRAM)
    float4 vs[4];
    #pragma unroll
    for (int j = 0; j < 4; ++j)
        vs[j] = __ldcs(x4 + base_s + j * 256u);

    float sred[4];
    if (rc >= 0) {
        const unsigned int base_r = (unsigned int)rc * CHUNK_F4 + i0;
        #pragma unroll
        for (int j = 0; j < 4; ++j) {
            const float4 v = x4[base_r + j * 256u];     // default: keep in L2
            sred[j] = (v.x + v.y) + (v.z + v.w);
        }
    }

    // slice sub-index per j, via compares (no divisions)
    int eidx[4];
    #pragma unroll
    for (int j = 0; j < 4; ++j) {
        const unsigned int idx = i0 + j * 256u;
        eidx[j] = (idx >= bd1) + (idx >= bd2);
    }

    // reduce-accumulate chunk rc (independent of e; before the gate)
    if (rc >= 0) {
        #pragma unroll
        for (int j = 0; j < 4; ++j) {
            float s  = sred[j];
            int  key = eidx[j];
            #pragma unroll
            for (int off = 16; off > 0; off >>= 1) {
                const float v2 = __shfl_down_sync(0xFFFFFFFFu, s, off);
                const int   k2 = __shfl_down_sync(0xFFFFFFFFu, key, off);
                if (lane + off < 32 && k2 == key) s += v2;
            }
            const int keyprev = __shfl_up_sync(0xFFFFFFFFu, key, 1);
            if (lane == 0 || keyprev != key)
                atomicAdd(&d_sq[rc * CHUNK_SLICES + slice_lo + eidx[j]], s);
        }
    }

    // FC2-only prologue, gated on the hid-ready flag (cheap: 128B of w2/thread)
    __shared__ float e_s[3];
    const int gb  = sc * CHUNK_B + batch;
    const int nsl = (int)((i0b + 1023u) / 784u) - slice_lo + 1;  // <= 3
    if (tid < nsl) {
        while (atomicAdd(&d_flag[gb], 0u) != tag) __nanosleep(32);
        __threadfence();                                 // acquire d_hid
        const int ch = (slice_lo + tid) & (C - 1);
        float a = __ldg(&b2[ch]);
        const float* __restrict__ hp  = d_hid + (size_t)gb * CR;
        const float4* __restrict__ wv =
            reinterpret_cast<const float4*>(w2 + (size_t)ch * CR);
        #pragma unroll
        for (int j = 0; j < CR / 4; ++j) {
            const float4 w = __ldg(&wv[j]);
            a = fmaf(__ldcg(&hp[4 * j + 0]), w.x, a);
            a = fmaf(__ldcg(&hp[4 * j + 1]), w.y, a);
            a = fmaf(__ldcg(&hp[4 * j + 2]), w.z, a);
            a = fmaf(__ldcg(&hp[4 * j + 3]), w.w, a);
        }
        e_s[tid] = 1.0f / (1.0f + __expf(-a));
    }
    __syncthreads();                                     // before stores only

    // scale + store; nothing after these stores
    #pragma unroll
    for (int j = 0; j < 4; ++j) {
        const float e = e_s[eidx[j]];
        float4 r = vs[j];
        r.x *= e; r.y *= e; r.z *= e; r.w *= e;
        __stcs(o4 + base_s + j * 256u, r);
    }
}

// ---------------------------------------------------------------------------
extern "C" void kernel_launch(void* const* d_in, const int* in_sizes, int n_in,
                              void* d_out, int out_size) {
    const float* x  = (const float*)d_in[0];
    const float* w1 = (const float*)d_in[1];
    const float* b1 = (const float*)d_in[2];
    const float* w2 = (const float*)d_in[3];
    const float* b2 = (const float*)d_in[4];
    float* out = (float*)d_out;

    se_reduce0<<<CHUNK_SLICES, 128>>>(x);
    for (int c = 0; c < NCHUNK; ++c) {
        const int rc = (c + 1 < NCHUNK) ? c + 1 : -1;
        se_sa<<<NSTREAM + CHUNK_B, 256>>>(x, out, w1, b1, w2, b2, c, rc);
    }
}